// round 16
// baseline (speedup 1.0000x reference)
#include <cuda_runtime.h>
#include <cuda_fp16.h>
#include <math.h>
#include <cstdint>

#define BB 2
#define NH 16
#define TT 2048
#define DD 64
#define EE 1024
#define SRC 128

// Scratch (no cudaMalloc allowed). All fp16 (Q pre-scaled by log2e/8).
__device__ __half g_qh[BB * NH * TT * DD];
__device__ __half g_kh[BB * NH * TT * DD];
__device__ __half g_vh[BB * NH * TT * DD];
__device__ __half g_xh[BB * TT * EE];
__device__ __half g_wh[3][EE * EE];

__device__ __forceinline__ uint32_t ph2(float lo, float hi) {
    __half2 h = __floats2half2_rn(lo, hi);
    return *(uint32_t*)&h;
}

// D += A(16x16) * B(16x8), fp16 inputs, fp32 accum.
__device__ __forceinline__ void mma_f16(
    float* d, uint32_t a0, uint32_t a1, uint32_t a2, uint32_t a3,
    uint32_t b0, uint32_t b1)
{
    asm volatile(
        "mma.sync.aligned.m16n8k16.row.col.f32.f16.f16.f32 "
        "{%0,%1,%2,%3}, {%4,%5,%6,%7}, {%8,%9}, {%0,%1,%2,%3};"
        : "+f"(d[0]), "+f"(d[1]), "+f"(d[2]), "+f"(d[3])
        : "r"(a0), "r"(a1), "r"(a2), "r"(a3), "r"(b0), "r"(b1));
}

__device__ __forceinline__ void ldm4(uint32_t* r, uint32_t a) {
    asm volatile("ldmatrix.sync.aligned.m8n8.x4.shared.b16 {%0,%1,%2,%3}, [%4];"
        : "=r"(r[0]), "=r"(r[1]), "=r"(r[2]), "=r"(r[3]) : "r"(a));
}
__device__ __forceinline__ void ldm4t(uint32_t* r, uint32_t a) {
    asm volatile("ldmatrix.sync.aligned.m8n8.x4.trans.shared.b16 {%0,%1,%2,%3}, [%4];"
        : "=r"(r[0]), "=r"(r[1]), "=r"(r[2]), "=r"(r[3]) : "r"(a));
}

__device__ __forceinline__ void cp_async16(uint32_t smem_addr, const void* gptr) {
    asm volatile("cp.async.cg.shared.global [%0], [%1], 16;"
                 :: "r"(smem_addr), "l"(gptr));
}
#define CP_COMMIT() asm volatile("cp.async.commit_group;" ::: "memory")
#define CP_WAIT(N)  asm volatile("cp.async.wait_group %0;" :: "n"(N) : "memory")

// ===========================================================================
// Convert kernel: plain fp32 -> fp16 of x and Wq/Wk/Wv.
// ===========================================================================
#define NX4 ((BB * TT * EE) / 4)   // 1048576
#define NW4 ((EE * EE) / 4)        // 262144

__global__ __launch_bounds__(256) void convert_kernel(
    const float* __restrict__ x,
    const float* __restrict__ Wq,
    const float* __restrict__ Wk,
    const float* __restrict__ Wv)
{
    const int idx = blockIdx.x * blockDim.x + threadIdx.x;
    const float* __restrict__ src;
    __half* __restrict__ dst;
    int li;
    if (idx < NX4) {
        src = x; dst = g_xh; li = idx;
    } else {
        const int t = idx - NX4;
        const int z = t / NW4;
        li = t - z * NW4;
        src = (z == 0) ? Wq : (z == 1) ? Wk : Wv;
        dst = g_wh[z];
    }
    const float4 v = ((const float4*)src)[li];
    uint2 o;
    o.x = ph2(v.x, v.y);
    o.y = ph2(v.z, v.w);
    ((uint2*)dst)[li] = o;
}

// ===========================================================================
// QKV projection: y = x @ W^T + b -> fp16 [B,H,T,D].  fp16 m16n8k16 mma.
// Block tile 128x128, 256 threads (8 warps as 4Mx2N; warp tile 32x64).
// FOUR-stage cp.async pipeline with 32-K chunks (slot 10240B, pitch 80B):
// same smem class as the 2-stage/64-K version (2 blocks/SM retained) but
// copy latency now has 3 compute-chunks of cover.
// Q output pre-scaled by log2e/8 (softmax runs in exp2 domain).
// ===========================================================================
#define GROWB 80u                  // bytes per smem row (32 halfs + 16B pad)
#define GSLOT 10240u               // 128 * 80
#define G_A(s) ((uint32_t)(s) * GSLOT)
#define G_B(s) (4u * GSLOT + (uint32_t)(s) * GSLOT)
#define GEMM_SMEM_BYTES 81920
#define NCH 32                     // EE / 32

__global__ __launch_bounds__(256, 2) void qkv_gemm_tc(
    const float* __restrict__ bq,
    const float* __restrict__ bk,
    const float* __restrict__ bv)
{
    extern __shared__ char smc[];

    const int z = blockIdx.z;
    const __half* __restrict__ Wt  = g_wh[z];
    const float* __restrict__ bias = (z == 0) ? bq : (z == 1) ? bk : bv;
    __half* __restrict__ dst       = (z == 0) ? g_qh : (z == 1) ? g_kh : g_vh;
    const float osc = (z == 0) ? 0.125f * 1.44269504f : 1.0f;

    const int m0 = blockIdx.y * 128;
    const int n0 = blockIdx.x * 128;
    const int tid = threadIdx.x;
    const int lane = tid & 31;
    const int wid = tid >> 5;
    const int wm = wid & 3;        // 0..3 : M warp (32 rows)
    const int wn = wid >> 2;       // 0..1 : N warp (64 cols)
    const int lr = lane >> 2;      // 0..7
    const int lc = lane & 3;       // 0..3

    const uint32_t smb = (uint32_t)__cvta_generic_to_shared(smc);

    const int a_row = lane & 15;
    const int a_off = (lane >> 4) * 16;
    const int b_row = ((lane >> 4) * 8) + (lane & 7);
    const int b_off = ((lane >> 3) & 1) * 16;

    // per-chunk copy: 128 rows x 4 x16B = 512 cp per tile; 2 per thread each
    const int cprow0 = tid >> 2;           // id = tid      -> rows 0..63
    const int cpch0 = tid & 3;
    const int cprow1 = (tid + 256) >> 2;   // id = tid+256  -> rows 64..127
    const int cpch1 = tid & 3;

    // prologue: issue chunks 0, 1, 2
    #pragma unroll
    for (int pc = 0; pc < 3; pc++) {
        const int k0 = pc * 32;
        cp_async16(smb + G_A(pc) + cprow0 * GROWB + cpch0 * 16,
                   &g_xh[(size_t)(m0 + cprow0) * EE + k0 + cpch0 * 8]);
        cp_async16(smb + G_A(pc) + cprow1 * GROWB + cpch1 * 16,
                   &g_xh[(size_t)(m0 + cprow1) * EE + k0 + cpch1 * 8]);
        cp_async16(smb + G_B(pc) + cprow0 * GROWB + cpch0 * 16,
                   &Wt[(size_t)(n0 + cprow0) * EE + k0 + cpch0 * 8]);
        cp_async16(smb + G_B(pc) + cprow1 * GROWB + cpch1 * 16,
                   &Wt[(size_t)(n0 + cprow1) * EE + k0 + cpch1 * 8]);
        CP_COMMIT();
    }

    float acc[2][8][4] = {};

    #pragma unroll 1
    for (int c = 0; c < NCH; c++) {
        if (c <= NCH - 3)      { CP_WAIT(2); }   // chunk c landed; c+1,c+2 fly
        else if (c == NCH - 2) { CP_WAIT(1); }
        else                   { CP_WAIT(0); }
        __syncthreads();   // all warps done with chunk c-1 -> slot (c+3)%4 free

        if (c + 3 < NCH) {
            const int s = (c + 3) & 3;
            const int k0 = (c + 3) * 32;
            cp_async16(smb + G_A(s) + cprow0 * GROWB + cpch0 * 16,
                       &g_xh[(size_t)(m0 + cprow0) * EE + k0 + cpch0 * 8]);
            cp_async16(smb + G_A(s) + cprow1 * GROWB + cpch1 * 16,
                       &g_xh[(size_t)(m0 + cprow1) * EE + k0 + cpch1 * 8]);
            cp_async16(smb + G_B(s) + cprow0 * GROWB + cpch0 * 16,
                       &Wt[(size_t)(n0 + cprow0) * EE + k0 + cpch0 * 8]);
            cp_async16(smb + G_B(s) + cprow1 * GROWB + cpch1 * 16,
                       &Wt[(size_t)(n0 + cprow1) * EE + k0 + cpch1 * 8]);
            CP_COMMIT();
        }

        const uint32_t A = smb + G_A(c & 3);
        const uint32_t B = smb + G_B(c & 3);

        // A fragments: 2 mt x 2 ks
        uint32_t av[2][2][4];
        #pragma unroll
        for (int mt = 0; mt < 2; mt++)
            #pragma unroll
            for (int ks = 0; ks < 2; ks++)
                ldm4(av[mt][ks],
                     A + (wm * 32 + mt * 16 + a_row) * GROWB + ks * 32 + a_off);

        #pragma unroll
        for (int ks = 0; ks < 2; ks++) {
            #pragma unroll
            for (int jp = 0; jp < 4; jp++) {
                uint32_t bf[4];
                ldm4(bf, B + (wn * 64 + jp * 16 + b_row) * GROWB + ks * 32 + b_off);
                mma_f16(acc[0][2 * jp],     av[0][ks][0], av[0][ks][1], av[0][ks][2], av[0][ks][3], bf[0], bf[1]);
                mma_f16(acc[0][2 * jp + 1], av[0][ks][0], av[0][ks][1], av[0][ks][2], av[0][ks][3], bf[2], bf[3]);
                mma_f16(acc[1][2 * jp],     av[1][ks][0], av[1][ks][1], av[1][ks][2], av[1][ks][3], bf[0], bf[1]);
                mma_f16(acc[1][2 * jp + 1], av[1][ks][0], av[1][ks][1], av[1][ks][2], av[1][ks][3], bf[2], bf[3]);
            }
        }
    }

    #pragma unroll
    for (int mt = 0; mt < 2; mt++) {
        #pragma unroll
        for (int j = 0; j < 8; j++) {
            const int N = n0 + wn * 64 + j * 8 + 2 * lc;
            const int h = N >> 6, d = N & 63;
            const float b0 = __ldg(&bias[N]), b1 = __ldg(&bias[N + 1]);
            #pragma unroll
            for (int half_ = 0; half_ < 2; half_++) {
                const int M = m0 + wm * 32 + mt * 16 + lr + half_ * 8;
                const int bb = M >> 11, t = M & (TT - 1);
                const uint32_t hv = ph2((acc[mt][j][half_ * 2 + 0] + b0) * osc,
                                        (acc[mt][j][half_ * 2 + 1] + b1) * osc);
                *(uint32_t*)&dst[(((size_t)(bb * NH + h) * TT) + t) * DD + d] = hv;
            }
        }
    }
}

// ===========================================================================
// Flash attention, prefix-causal band (key j valid iff j <= i + SRC).
// One block = (b, h, 256-query tile). 512 threads (16 warps); warp = 16 rows.
// fp16 m16n8k16; K/V double-buffered cp.async (2-stage). P stays in
// REGISTERS (S-output frag == A-input frag for P@V after ph2 packing).
// Softmax in exp2 domain (Q pre-scaled by log2e/8).  [identical to R15]
// ===========================================================================
#define QROWS 256
#define AROWB 144                     // bytes per smem row (64 halfs + pad)
#define AS_QS 0u                      // 256 rows -> 36864 B
#define AS_K0 36864u
#define AS_K1 46080u
#define AS_V0 55296u
#define AS_V1 64512u
#define ATTN_SMEM_BYTES 73728

__global__ __launch_bounds__(512, 1) void attn_kernel(float* __restrict__ out)
{
    extern __shared__ char smc[];

    const int qtile = gridDim.x - 1 - blockIdx.x;  // heavy tiles first
    const int h = blockIdx.y;
    const int b = blockIdx.z;
    const int qs = qtile * QROWS;

    const __half* __restrict__ Qb = g_qh + (size_t)(b * NH + h) * TT * DD;
    const __half* __restrict__ Kb = g_kh + (size_t)(b * NH + h) * TT * DD;
    const __half* __restrict__ Vb = g_vh + (size_t)(b * NH + h) * TT * DD;

    const int tid = threadIdx.x;
    const int lane = tid & 31;
    const int w = tid >> 5;        // warp id 0..15: rows 16w..16w+15
    const int lr = lane >> 2;      // 0..7
    const int lc = lane & 3;       // 0..3

    const uint32_t smb = (uint32_t)__cvta_generic_to_shared(smc);

    const int a_row = lane & 15;
    const int a_off = (lane >> 4) * 16;
    const int b_row = ((lane >> 4) * 8) + (lane & 7);
    const int b_off = ((lane >> 3) & 1) * 16;

    // K/V cooperative copy mapping: 64 rows x 8 chunks; 1 x16B per thread each
    const int kvrow = tid >> 3;
    const int kvch = tid & 7;

    // ---- prologue: Q (group), then K/V tile 0 (group) ----
    #pragma unroll
    for (int i = 0; i < 4; i++) {
        const int id = tid + i * 512;
        const int row = id >> 3;
        const int ch = id & 7;
        cp_async16(smb + AS_QS + row * AROWB + ch * 16,
                   &Qb[(size_t)(qs + row) * DD + ch * 8]);
    }
    CP_COMMIT();
    cp_async16(smb + AS_K0 + kvrow * AROWB + kvch * 16, &Kb[(size_t)kvrow * DD + kvch * 8]);
    cp_async16(smb + AS_V0 + kvrow * AROWB + kvch * 16, &Vb[(size_t)kvrow * DD + kvch * 8]);
    CP_COMMIT();

    CP_WAIT(1);          // Q landed (tile0 may still be in flight)
    __syncthreads();

    // hoist Q fragments: 4 ksteps x 4 regs
    uint32_t qa[4][4];
    #pragma unroll
    for (int ks = 0; ks < 4; ks++)
        ldm4(qa[ks], smb + AS_QS + (w * 16 + a_row) * AROWB + ks * 32 + a_off);

    float o[8][4] = {};
    float m_lo = -1e30f, m_hi = -1e30f, l_lo = 0.0f, l_hi = 0.0f;

    const int ntiles = min(TT / 64, qtile * 4 + 6);

    #pragma unroll 1
    for (int jt = 0; jt < ntiles; jt++) {
        const int kst = jt * 64;

        CP_WAIT(0);        // tile jt landed
        __syncthreads();   // + all warps done with jt-1 (buffers reusable)

        if (jt + 1 < ntiles) {
            const int nk = (jt + 1) * 64;
            const uint32_t koff = ((jt + 1) & 1) ? AS_K1 : AS_K0;
            const uint32_t voff = ((jt + 1) & 1) ? AS_V1 : AS_V0;
            cp_async16(smb + koff + kvrow * AROWB + kvch * 16,
                       &Kb[(size_t)(nk + kvrow) * DD + kvch * 8]);
            cp_async16(smb + voff + kvrow * AROWB + kvch * 16,
                       &Vb[(size_t)(nk + kvrow) * DD + kvch * 8]);
            CP_COMMIT();
        }

        const uint32_t Ks = smb + ((jt & 1) ? AS_K1 : AS_K0);
        const uint32_t Vs = smb + ((jt & 1) ? AS_V1 : AS_V0);

        // ---- S = Q @ K^T (logits already in log2e units) ----
        float s[8][4] = {};
        #pragma unroll
        for (int ks = 0; ks < 4; ks++) {
            #pragma unroll
            for (int jp = 0; jp < 4; jp++) {
                uint32_t bf[4];
                ldm4(bf, Ks + (jp * 16 + b_row) * AROWB + ks * 32 + b_off);
                mma_f16(s[2 * jp],     qa[ks][0], qa[ks][1], qa[ks][2], qa[ks][3], bf[0], bf[1]);
                mma_f16(s[2 * jp + 1], qa[ks][0], qa[ks][1], qa[ks][2], qa[ks][3], bf[2], bf[3]);
            }
        }

        // ---- mask (partially-banded tiles only) ----
        if ((kst + 63) > (qs + SRC)) {
            const int rlo = qs + w * 16 + lr;
            #pragma unroll
            for (int j = 0; j < 8; j++) {
                const int c0 = kst + j * 8 + 2 * lc;
                if (c0     > rlo + SRC)     s[j][0] = -1e30f;
                if (c0 + 1 > rlo + SRC)     s[j][1] = -1e30f;
                if (c0     > rlo + 8 + SRC) s[j][2] = -1e30f;
                if (c0 + 1 > rlo + 8 + SRC) s[j][3] = -1e30f;
            }
        }

        // ---- online softmax, exp2 domain; P packed straight to A-frags ----
        float mx_lo = -1e30f, mx_hi = -1e30f;
        #pragma unroll
        for (int j = 0; j < 8; j++) {
            mx_lo = fmaxf(mx_lo, fmaxf(s[j][0], s[j][1]));
            mx_hi = fmaxf(mx_hi, fmaxf(s[j][2], s[j][3]));
        }
        #pragma unroll
        for (int off = 1; off <= 2; off <<= 1) {
            mx_lo = fmaxf(mx_lo, __shfl_xor_sync(0xffffffffu, mx_lo, off));
            mx_hi = fmaxf(mx_hi, __shfl_xor_sync(0xffffffffu, mx_hi, off));
        }
        const float mn_lo = fmaxf(m_lo, mx_lo);
        const float mn_hi = fmaxf(m_hi, mx_hi);
        const float al_lo = exp2f(m_lo - mn_lo);
        const float al_hi = exp2f(m_hi - mn_hi);
        m_lo = mn_lo; m_hi = mn_hi;

        float sum_lo = 0.0f, sum_hi = 0.0f;
        uint32_t pa[4][4];   // A-fragments of P for the 4 PV k-steps
        #pragma unroll
        for (int j = 0; j < 8; j++) {
            float p0 = exp2f(s[j][0] - mn_lo);
            float p1 = exp2f(s[j][1] - mn_lo);
            float p2 = exp2f(s[j][2] - mn_hi);
            float p3 = exp2f(s[j][3] - mn_hi);
            sum_lo += p0 + p1;
            sum_hi += p2 + p3;
            pa[j >> 1][(j & 1) * 2 + 0] = ph2(p0, p1);   // rows r
            pa[j >> 1][(j & 1) * 2 + 1] = ph2(p2, p3);   // rows r+8
            o[j][0] *= al_lo; o[j][1] *= al_lo;
            o[j][2] *= al_hi; o[j][3] *= al_hi;
        }
        #pragma unroll
        for (int off = 1; off <= 2; off <<= 1) {
            sum_lo += __shfl_xor_sync(0xffffffffu, sum_lo, off);
            sum_hi += __shfl_xor_sync(0xffffffffu, sum_hi, off);
        }
        l_lo = l_lo * al_lo + sum_lo;
        l_hi = l_hi * al_hi + sum_hi;

        // ---- O += P @ V (P from registers; V fragments via ldmatrix.trans) ----
        #pragma unroll
        for (int ks = 0; ks < 4; ks++) {
            #pragma unroll
            for (int jp = 0; jp < 4; jp++) {
                uint32_t vf[4];
                ldm4t(vf, Vs + (ks * 16 + a_row) * AROWB + (jp * 2 + (lane >> 4)) * 16);
                mma_f16(o[2 * jp],     pa[ks][0], pa[ks][1], pa[ks][2], pa[ks][3], vf[0], vf[1]);
                mma_f16(o[2 * jp + 1], pa[ks][0], pa[ks][1], pa[ks][2], pa[ks][3], vf[2], vf[3]);
            }
        }
    }

    // ---- finalize: scale by 1/l, write out ----
    const float li_lo = 1.0f / l_lo;
    const float li_hi = 1.0f / l_hi;
    const int t_lo = qs + w * 16 + lr;
    #pragma unroll
    for (int j = 0; j < 8; j++) {
        const int d = j * 8 + 2 * lc;
        float2 v0 = make_float2(o[j][0] * li_lo, o[j][1] * li_lo);
        float2 v1 = make_float2(o[j][2] * li_hi, o[j][3] * li_hi);
        *(float2*)&out[((size_t)(b * TT + t_lo)) * EE + h * DD + d] = v0;
        *(float2*)&out[((size_t)(b * TT + t_lo + 8)) * EE + h * DD + d] = v1;
    }
}

// ---------------------------------------------------------------------------
extern "C" void kernel_launch(void* const* d_in, const int* in_sizes, int n_in,
                              void* d_out, int out_size)
{
    (void)in_sizes; (void)n_in; (void)out_size;
    const float* x  = (const float*)d_in[0];
    const float* Wq = (const float*)d_in[1];
    const float* bq = (const float*)d_in[2];
    const float* Wk = (const float*)d_in[3];
    const float* bk = (const float*)d_in[4];
    const float* Wv = (const float*)d_in[5];
    const float* bv = (const float*)d_in[6];
    float* out = (float*)d_out;

    cudaFuncSetAttribute(qkv_gemm_tc,
                         cudaFuncAttributeMaxDynamicSharedMemorySize,
                         GEMM_SMEM_BYTES);
    cudaFuncSetAttribute(attn_kernel,
                         cudaFuncAttributeMaxDynamicSharedMemorySize,
                         ATTN_SMEM_BYTES);

    const int total4 = NX4 + 3 * NW4;               // 1,835,008
    convert_kernel<<<total4 / 256, 256>>>(x, Wq, Wk, Wv);

    dim3 ggrid(EE / 128, (BB * TT) / 128, 3);       // (8, 32, 3)
    qkv_gemm_tc<<<ggrid, 256, GEMM_SMEM_BYTES>>>(bq, bk, bv);

    dim3 agrid(TT / QROWS, NH, BB);                 // (8, 16, 2)
    attn_kernel<<<agrid, 512, ATTN_SMEM_BYTES>>>(out);
}

// round 17
// speedup vs baseline: 1.2175x; 1.2175x over previous
#include <cuda_runtime.h>
#include <cuda_fp16.h>
#include <math.h>
#include <cstdint>

#define BB 2
#define NH 16
#define TT 2048
#define DD 64
#define EE 1024
#define SRC 128

// Scratch (no cudaMalloc allowed). All fp16 (Q pre-scaled by log2e/8).
__device__ __half g_qh[BB * NH * TT * DD];
__device__ __half g_kh[BB * NH * TT * DD];
__device__ __half g_vh[BB * NH * TT * DD];
__device__ __half g_xh[BB * TT * EE];
__device__ __half g_wh[3][EE * EE];
__device__ unsigned int g_ctr;      // persistent-attn work counter

__device__ __forceinline__ uint32_t ph2(float lo, float hi) {
    __half2 h = __floats2half2_rn(lo, hi);
    return *(uint32_t*)&h;
}

// D += A(16x16) * B(16x8), fp16 inputs, fp32 accum.
__device__ __forceinline__ void mma_f16(
    float* d, uint32_t a0, uint32_t a1, uint32_t a2, uint32_t a3,
    uint32_t b0, uint32_t b1)
{
    asm volatile(
        "mma.sync.aligned.m16n8k16.row.col.f32.f16.f16.f32 "
        "{%0,%1,%2,%3}, {%4,%5,%6,%7}, {%8,%9}, {%0,%1,%2,%3};"
        : "+f"(d[0]), "+f"(d[1]), "+f"(d[2]), "+f"(d[3])
        : "r"(a0), "r"(a1), "r"(a2), "r"(a3), "r"(b0), "r"(b1));
}

__device__ __forceinline__ void ldm4(uint32_t* r, uint32_t a) {
    asm volatile("ldmatrix.sync.aligned.m8n8.x4.shared.b16 {%0,%1,%2,%3}, [%4];"
        : "=r"(r[0]), "=r"(r[1]), "=r"(r[2]), "=r"(r[3]) : "r"(a));
}
__device__ __forceinline__ void ldm4t(uint32_t* r, uint32_t a) {
    asm volatile("ldmatrix.sync.aligned.m8n8.x4.trans.shared.b16 {%0,%1,%2,%3}, [%4];"
        : "=r"(r[0]), "=r"(r[1]), "=r"(r[2]), "=r"(r[3]) : "r"(a));
}

__device__ __forceinline__ void cp_async16(uint32_t smem_addr, const void* gptr) {
    asm volatile("cp.async.cg.shared.global [%0], [%1], 16;"
                 :: "r"(smem_addr), "l"(gptr));
}
#define CP_COMMIT() asm volatile("cp.async.commit_group;" ::: "memory")
#define CP_WAIT(N)  asm volatile("cp.async.wait_group %0;" :: "n"(N) : "memory")

// ===========================================================================
// Convert kernel: plain fp32 -> fp16 of x and Wq/Wk/Wv.
// ===========================================================================
#define NX4 ((BB * TT * EE) / 4)   // 1048576
#define NW4 ((EE * EE) / 4)        // 262144

__global__ __launch_bounds__(256) void convert_kernel(
    const float* __restrict__ x,
    const float* __restrict__ Wq,
    const float* __restrict__ Wk,
    const float* __restrict__ Wv)
{
    const int idx = blockIdx.x * blockDim.x + threadIdx.x;
    const float* __restrict__ src;
    __half* __restrict__ dst;
    int li;
    if (idx < NX4) {
        src = x; dst = g_xh; li = idx;
    } else {
        const int t = idx - NX4;
        const int z = t / NW4;
        li = t - z * NW4;
        src = (z == 0) ? Wq : (z == 1) ? Wk : Wv;
        dst = g_wh[z];
    }
    const float4 v = ((const float4*)src)[li];
    uint2 o;
    o.x = ph2(v.x, v.y);
    o.y = ph2(v.z, v.w);
    ((uint2*)dst)[li] = o;
}

// ===========================================================================
// QKV projection: y = x @ W^T + b -> fp16 [B,H,T,D].  fp16 m16n8k16 mma.
// Block tile 128x128, 256 threads (8 warps as 4Mx2N; warp tile 32x64).
// 64-K chunks, TWO-stage cp.async pipeline (R15/R12 structure — best).
// Q output pre-scaled by log2e/8 (softmax runs in exp2 domain).
// ===========================================================================
#define GROWB 144                  // bytes per smem row (64 halfs + pad)
#define G_A0 0u
#define G_A1 18432u
#define G_B0 36864u
#define G_B1 55296u
#define GEMM_SMEM_BYTES 73728

__global__ __launch_bounds__(256, 2) void qkv_gemm_tc(
    const float* __restrict__ bq,
    const float* __restrict__ bk,
    const float* __restrict__ bv)
{
    extern __shared__ char smc[];

    const int z = blockIdx.z;
    const __half* __restrict__ Wt  = g_wh[z];
    const float* __restrict__ bias = (z == 0) ? bq : (z == 1) ? bk : bv;
    __half* __restrict__ dst       = (z == 0) ? g_qh : (z == 1) ? g_kh : g_vh;
    const float osc = (z == 0) ? 0.125f * 1.44269504f : 1.0f;

    const int m0 = blockIdx.y * 128;
    const int n0 = blockIdx.x * 128;
    const int tid = threadIdx.x;
    const int lane = tid & 31;
    const int wid = tid >> 5;
    const int wm = wid & 3;        // 0..3 : M warp (32 rows)
    const int wn = wid >> 2;       // 0..1 : N warp (64 cols)
    const int lr = lane >> 2;      // 0..7
    const int lc = lane & 3;       // 0..3

    const uint32_t smb = (uint32_t)__cvta_generic_to_shared(smc);

    const int a_row = lane & 15;
    const int a_off = (lane >> 4) * 16;
    const int b_row = ((lane >> 4) * 8) + (lane & 7);
    const int b_off = ((lane >> 3) & 1) * 16;

    #pragma unroll
    for (int i = 0; i < 4; i++) {
        const int id = tid + i * 256;
        const int row = id >> 3;
        const int ch = id & 7;
        cp_async16(smb + G_A0 + row * GROWB + ch * 16,
                   &g_xh[(size_t)(m0 + row) * EE + ch * 8]);
        cp_async16(smb + G_B0 + row * GROWB + ch * 16,
                   &Wt[(size_t)(n0 + row) * EE + ch * 8]);
    }
    CP_COMMIT();

    float acc[2][8][4] = {};

    #pragma unroll 1
    for (int c = 0; c < EE / 64; c++) {
        CP_WAIT(0);
        __syncthreads();

        if (c + 1 < EE / 64) {
            const int k0 = (c + 1) * 64;
            const uint32_t aoff = ((c + 1) & 1) ? G_A1 : G_A0;
            const uint32_t boff = ((c + 1) & 1) ? G_B1 : G_B0;
            #pragma unroll
            for (int i = 0; i < 4; i++) {
                const int id = tid + i * 256;
                const int row = id >> 3;
                const int ch = id & 7;
                cp_async16(smb + aoff + row * GROWB + ch * 16,
                           &g_xh[(size_t)(m0 + row) * EE + k0 + ch * 8]);
                cp_async16(smb + boff + row * GROWB + ch * 16,
                           &Wt[(size_t)(n0 + row) * EE + k0 + ch * 8]);
            }
            CP_COMMIT();
        }

        const uint32_t A = smb + ((c & 1) ? G_A1 : G_A0);
        const uint32_t B = smb + ((c & 1) ? G_B1 : G_B0);

        uint32_t av[2][4][4];
        #pragma unroll
        for (int mt = 0; mt < 2; mt++)
            #pragma unroll
            for (int ks = 0; ks < 4; ks++)
                ldm4(av[mt][ks],
                     A + (wm * 32 + mt * 16 + a_row) * GROWB + ks * 32 + a_off);

        #pragma unroll
        for (int ks = 0; ks < 4; ks++) {
            #pragma unroll
            for (int jp = 0; jp < 4; jp++) {
                uint32_t bf[4];
                ldm4(bf, B + (wn * 64 + jp * 16 + b_row) * GROWB + ks * 32 + b_off);
                mma_f16(acc[0][2 * jp],     av[0][ks][0], av[0][ks][1], av[0][ks][2], av[0][ks][3], bf[0], bf[1]);
                mma_f16(acc[0][2 * jp + 1], av[0][ks][0], av[0][ks][1], av[0][ks][2], av[0][ks][3], bf[2], bf[3]);
                mma_f16(acc[1][2 * jp],     av[1][ks][0], av[1][ks][1], av[1][ks][2], av[1][ks][3], bf[0], bf[1]);
                mma_f16(acc[1][2 * jp + 1], av[1][ks][0], av[1][ks][1], av[1][ks][2], av[1][ks][3], bf[2], bf[3]);
            }
        }
    }

    #pragma unroll
    for (int mt = 0; mt < 2; mt++) {
        #pragma unroll
        for (int j = 0; j < 8; j++) {
            const int N = n0 + wn * 64 + j * 8 + 2 * lc;
            const int h = N >> 6, d = N & 63;
            const float b0 = __ldg(&bias[N]), b1 = __ldg(&bias[N + 1]);
            #pragma unroll
            for (int half_ = 0; half_ < 2; half_++) {
                const int M = m0 + wm * 32 + mt * 16 + lr + half_ * 8;
                const int bb = M >> 11, t = M & (TT - 1);
                const uint32_t hv = ph2((acc[mt][j][half_ * 2 + 0] + b0) * osc,
                                        (acc[mt][j][half_ * 2 + 1] + b1) * osc);
                *(uint32_t*)&dst[(((size_t)(bb * NH + h) * TT) + t) * DD + d] = hv;
            }
        }
    }
}

// ===========================================================================
// Flash attention, prefix-causal band (key j valid iff j <= i + SRC).
// PERSISTENT: 148 blocks x 512 threads; work items (qtile,h,b) pulled
// heavy-first from a global atomic counter (reset per launch by memset).
// Item -> qtile = 7 - item/32 (descending work), h = item%16, b = (item/16)%2.
// Per item: identical pipeline to R15 (fp16 m16n8k16, 2-stage K/V cp.async,
// register-resident P, exp2-domain softmax).
// ===========================================================================
#define QROWS 256
#define NITEMS ((TT / QROWS) * NH * BB)   // 256
#define AROWB 144
#define AS_QS 0u
#define AS_K0 36864u
#define AS_K1 46080u
#define AS_V0 55296u
#define AS_V1 64512u
#define ATTN_SMEM_BYTES 73732             // +4 for the item broadcast slot
#define AS_ITEM 73728u

__global__ __launch_bounds__(512, 1) void attn_kernel(float* __restrict__ out)
{
    extern __shared__ char smc[];

    const int tid = threadIdx.x;
    const int lane = tid & 31;
    const int w = tid >> 5;        // warp id 0..15: rows 16w..16w+15
    const int lr = lane >> 2;      // 0..7
    const int lc = lane & 3;       // 0..3

    const uint32_t smb = (uint32_t)__cvta_generic_to_shared(smc);
    unsigned int* s_item = (unsigned int*)(smc + AS_ITEM);

    const int a_row = lane & 15;
    const int a_off = (lane >> 4) * 16;
    const int b_row = ((lane >> 4) * 8) + (lane & 7);
    const int b_off = ((lane >> 3) & 1) * 16;

    const int kvrow = tid >> 3;
    const int kvch = tid & 7;

    for (;;) {
        if (tid == 0) *s_item = atomicAdd(&g_ctr, 1u);
        __syncthreads();                     // s_item visible; prev item done
        const unsigned int item = *s_item;
        if (item >= NITEMS) break;

        const int qtile = 7 - (int)(item >> 5);        // heavy (banded) first
        const int sub = (int)(item & 31);
        const int h = sub & 15;
        const int b = sub >> 4;
        const int qs = qtile * QROWS;

        const __half* __restrict__ Qb = g_qh + (size_t)(b * NH + h) * TT * DD;
        const __half* __restrict__ Kb = g_kh + (size_t)(b * NH + h) * TT * DD;
        const __half* __restrict__ Vb = g_vh + (size_t)(b * NH + h) * TT * DD;

        // ---- prologue: Q (group), then K/V tile 0 (group) ----
        #pragma unroll
        for (int i = 0; i < 4; i++) {
            const int id = tid + i * 512;
            const int row = id >> 3;
            const int ch = id & 7;
            cp_async16(smb + AS_QS + row * AROWB + ch * 16,
                       &Qb[(size_t)(qs + row) * DD + ch * 8]);
        }
        CP_COMMIT();
        cp_async16(smb + AS_K0 + kvrow * AROWB + kvch * 16, &Kb[(size_t)kvrow * DD + kvch * 8]);
        cp_async16(smb + AS_V0 + kvrow * AROWB + kvch * 16, &Vb[(size_t)kvrow * DD + kvch * 8]);
        CP_COMMIT();

        CP_WAIT(1);
        __syncthreads();

        uint32_t qa[4][4];
        #pragma unroll
        for (int ks = 0; ks < 4; ks++)
            ldm4(qa[ks], smb + AS_QS + (w * 16 + a_row) * AROWB + ks * 32 + a_off);

        float o[8][4] = {};
        float m_lo = -1e30f, m_hi = -1e30f, l_lo = 0.0f, l_hi = 0.0f;

        const int ntiles = min(TT / 64, qtile * 4 + 6);

        #pragma unroll 1
        for (int jt = 0; jt < ntiles; jt++) {
            const int kst = jt * 64;

            CP_WAIT(0);        // tile jt landed
            __syncthreads();   // + all warps done with jt-1

            if (jt + 1 < ntiles) {
                const int nk = (jt + 1) * 64;
                const uint32_t koff = ((jt + 1) & 1) ? AS_K1 : AS_K0;
                const uint32_t voff = ((jt + 1) & 1) ? AS_V1 : AS_V0;
                cp_async16(smb + koff + kvrow * AROWB + kvch * 16,
                           &Kb[(size_t)(nk + kvrow) * DD + kvch * 8]);
                cp_async16(smb + voff + kvrow * AROWB + kvch * 16,
                           &Vb[(size_t)(nk + kvrow) * DD + kvch * 8]);
                CP_COMMIT();
            }

            const uint32_t Ks = smb + ((jt & 1) ? AS_K1 : AS_K0);
            const uint32_t Vs = smb + ((jt & 1) ? AS_V1 : AS_V0);

            // ---- S = Q @ K^T ----
            float s[8][4] = {};
            #pragma unroll
            for (int ks = 0; ks < 4; ks++) {
                #pragma unroll
                for (int jp = 0; jp < 4; jp++) {
                    uint32_t bf[4];
                    ldm4(bf, Ks + (jp * 16 + b_row) * AROWB + ks * 32 + b_off);
                    mma_f16(s[2 * jp],     qa[ks][0], qa[ks][1], qa[ks][2], qa[ks][3], bf[0], bf[1]);
                    mma_f16(s[2 * jp + 1], qa[ks][0], qa[ks][1], qa[ks][2], qa[ks][3], bf[2], bf[3]);
                }
            }

            // ---- mask (partially-banded tiles only) ----
            if ((kst + 63) > (qs + SRC)) {
                const int rlo = qs + w * 16 + lr;
                #pragma unroll
                for (int j = 0; j < 8; j++) {
                    const int c0 = kst + j * 8 + 2 * lc;
                    if (c0     > rlo + SRC)     s[j][0] = -1e30f;
                    if (c0 + 1 > rlo + SRC)     s[j][1] = -1e30f;
                    if (c0     > rlo + 8 + SRC) s[j][2] = -1e30f;
                    if (c0 + 1 > rlo + 8 + SRC) s[j][3] = -1e30f;
                }
            }

            // ---- online softmax, exp2 domain; P packed to A-frags ----
            float mx_lo = -1e30f, mx_hi = -1e30f;
            #pragma unroll
            for (int j = 0; j < 8; j++) {
                mx_lo = fmaxf(mx_lo, fmaxf(s[j][0], s[j][1]));
                mx_hi = fmaxf(mx_hi, fmaxf(s[j][2], s[j][3]));
            }
            #pragma unroll
            for (int off = 1; off <= 2; off <<= 1) {
                mx_lo = fmaxf(mx_lo, __shfl_xor_sync(0xffffffffu, mx_lo, off));
                mx_hi = fmaxf(mx_hi, __shfl_xor_sync(0xffffffffu, mx_hi, off));
            }
            const float mn_lo = fmaxf(m_lo, mx_lo);
            const float mn_hi = fmaxf(m_hi, mx_hi);
            const float al_lo = exp2f(m_lo - mn_lo);
            const float al_hi = exp2f(m_hi - mn_hi);
            m_lo = mn_lo; m_hi = mn_hi;

            float sum_lo = 0.0f, sum_hi = 0.0f;
            uint32_t pa[4][4];
            #pragma unroll
            for (int j = 0; j < 8; j++) {
                float p0 = exp2f(s[j][0] - mn_lo);
                float p1 = exp2f(s[j][1] - mn_lo);
                float p2 = exp2f(s[j][2] - mn_hi);
                float p3 = exp2f(s[j][3] - mn_hi);
                sum_lo += p0 + p1;
                sum_hi += p2 + p3;
                pa[j >> 1][(j & 1) * 2 + 0] = ph2(p0, p1);
                pa[j >> 1][(j & 1) * 2 + 1] = ph2(p2, p3);
                o[j][0] *= al_lo; o[j][1] *= al_lo;
                o[j][2] *= al_hi; o[j][3] *= al_hi;
            }
            #pragma unroll
            for (int off = 1; off <= 2; off <<= 1) {
                sum_lo += __shfl_xor_sync(0xffffffffu, sum_lo, off);
                sum_hi += __shfl_xor_sync(0xffffffffu, sum_hi, off);
            }
            l_lo = l_lo * al_lo + sum_lo;
            l_hi = l_hi * al_hi + sum_hi;

            // ---- O += P @ V ----
            #pragma unroll
            for (int ks = 0; ks < 4; ks++) {
                #pragma unroll
                for (int jp = 0; jp < 4; jp++) {
                    uint32_t vf[4];
                    ldm4t(vf, Vs + (ks * 16 + a_row) * AROWB + (jp * 2 + (lane >> 4)) * 16);
                    mma_f16(o[2 * jp],     pa[ks][0], pa[ks][1], pa[ks][2], pa[ks][3], vf[0], vf[1]);
                    mma_f16(o[2 * jp + 1], pa[ks][0], pa[ks][1], pa[ks][2], pa[ks][3], vf[2], vf[3]);
                }
            }
        }

        // ---- finalize: scale by 1/l, write out ----
        const float li_lo = 1.0f / l_lo;
        const float li_hi = 1.0f / l_hi;
        const int t_lo = qs + w * 16 + lr;
        #pragma unroll
        for (int j = 0; j < 8; j++) {
            const int d = j * 8 + 2 * lc;
            float2 v0 = make_float2(o[j][0] * li_lo, o[j][1] * li_lo);
            float2 v1 = make_float2(o[j][2] * li_hi, o[j][3] * li_hi);
            *(float2*)&out[((size_t)(b * TT + t_lo)) * EE + h * DD + d] = v0;
            *(float2*)&out[((size_t)(b * TT + t_lo + 8)) * EE + h * DD + d] = v1;
        }
        __syncthreads();   // out writes done before s_item reuse next iter
    }
}

// ---------------------------------------------------------------------------
extern "C" void kernel_launch(void* const* d_in, const int* in_sizes, int n_in,
                              void* d_out, int out_size)
{
    (void)in_sizes; (void)n_in; (void)out_size;
    const float* x  = (const float*)d_in[0];
    const float* Wq = (const float*)d_in[1];
    const float* bq = (const float*)d_in[2];
    const float* Wk = (const float*)d_in[3];
    const float* bk = (const float*)d_in[4];
    const float* Wv = (const float*)d_in[5];
    const float* bv = (const float*)d_in[6];
    float* out = (float*)d_out;

    cudaFuncSetAttribute(qkv_gemm_tc,
                         cudaFuncAttributeMaxDynamicSharedMemorySize,
                         GEMM_SMEM_BYTES);
    cudaFuncSetAttribute(attn_kernel,
                         cudaFuncAttributeMaxDynamicSharedMemorySize,
                         ATTN_SMEM_BYTES);

    // reset persistent work counter (graph-capturable async memset)
    void* ctr_ptr = nullptr;
    cudaGetSymbolAddress(&ctr_ptr, g_ctr);
    cudaMemsetAsync(ctr_ptr, 0, sizeof(unsigned int));

    const int total4 = NX4 + 3 * NW4;               // 1,835,008
    convert_kernel<<<total4 / 256, 256>>>(x, Wq, Wk, Wv);

    dim3 ggrid(EE / 128, (BB * TT) / 128, 3);       // (8, 32, 3)
    qkv_gemm_tc<<<ggrid, 256, GEMM_SMEM_BYTES>>>(bq, bk, bv);

    attn_kernel<<<148, 512, ATTN_SMEM_BYTES>>>(out);
}